// round 7
// baseline (speedup 1.0000x reference)
#include <cuda_runtime.h>
#include <cuda_bf16.h>
#include <math.h>
#include <stdint.h>

// Problem constants
#define B_   4
#define U_   8192
#define E_   128
#define GH_  64
#define GW_  64
#define S_   (GH_*GW_)        // 4096
#define NB_  (B_*S_)          // 16384 buckets
#define NOFF (B_*U_)          // 32768 off-grid tokens
#define CAP_ 23               // MAX_PATCH-1 usable slots

// ---------------- scratch (device globals; no cudaMalloc allowed) ----------
__device__ float g_Koff[NOFF*E_];   // 16 MB
__device__ float g_Voff[NOFF*E_];   // 16 MB
__device__ float g_Kon [NB_*E_];    // 8 MB
__device__ float g_Von [NB_*E_];    // 8 MB
__device__ float g_Q   [S_*E_];     // 2 MB (shared across batch)
__device__ float g_attn[NB_*E_];    // 8 MB
__device__ int   g_counts[NB_];
__device__ int   g_members[NB_*CAP_];
__device__ float g_Kfake[E_];
__device__ float g_Vfake[E_];
// Pre-split bf16 weights, transposed + k-pair-packed for the mma B fragment:
// g_Wp[w][p][kk*128 + n] = bf16(W[2kk][n]) | bf16(W[2kk+1][n])<<16
// w: 0=Wq 1=Wk 2=Wv 3=Wo ; p: 0=hi 1=lo(residual)
__device__ uint32_t g_Wp[4][2][64*128];

// ---------------- helpers ----------------------------------------------------
__device__ __forceinline__ uint32_t pk2(float x, float y) {
    uint32_t lo = (uint32_t)__bfloat16_as_ushort(__float2bfloat16(x));
    uint32_t hi = (uint32_t)__bfloat16_as_ushort(__float2bfloat16(y));
    return lo | (hi << 16);
}
__device__ __forceinline__ float resid(float x) {
    return x - __bfloat162float(__float2bfloat16(x));
}
__device__ __forceinline__ void mma16816(float* c, const uint32_t* a,
                                         uint32_t b0, uint32_t b1) {
    asm volatile(
        "mma.sync.aligned.m16n8k16.row.col.f32.bf16.bf16.f32 "
        "{%0,%1,%2,%3}, {%4,%5,%6,%7}, {%8,%9}, {%0,%1,%2,%3};"
        : "+f"(c[0]), "+f"(c[1]), "+f"(c[2]), "+f"(c[3])
        : "r"(a[0]), "r"(a[1]), "r"(a[2]), "r"(a[3]), "r"(b0), "r"(b1));
}

// ---------------- Stage 1 (fused prep): wsplit + bucketize + fake proj ------
__global__ void __launch_bounds__(256) prep_kernel(const float* __restrict__ Wq,
                                                   const float* __restrict__ Wk,
                                                   const float* __restrict__ Wv,
                                                   const float* __restrict__ Wo,
                                                   const float* __restrict__ xoff,
                                                   const float* __restrict__ xon,
                                                   const float* __restrict__ fake) {
    const int blk = blockIdx.x;
    const int tid = threadIdx.x;

    if (blk < 4) {
        // ---- weight split/pack ----
        const float* W = (blk == 0) ? Wq : (blk == 1) ? Wk : (blk == 2) ? Wv : Wo;
        uint32_t* dh = g_Wp[blk][0];
        uint32_t* dl = g_Wp[blk][1];
        for (int idx = tid; idx < 64 * 128; idx += 256) {
            int kk = idx >> 7;
            int n  = idx & 127;
            float w0 = W[(2*kk)   * 128 + n];
            float w1 = W[(2*kk+1) * 128 + n];
            dh[idx] = pk2(w0, w1);
            dl[idx] = pk2(resid(w0), resid(w1));
        }
    } else if (blk < 132) {
        // ---- bucket assignment ----
        int i = (blk - 4) * 256 + tid;
        float ay0 = xon[0];
        float ay1 = xon[2*GW_];
        float ax0 = xon[1];
        float ax1 = xon[3];
        float x0 = xoff[2*i+0];
        float x1 = xoff[2*i+1];
        float r0 = rintf(__fdiv_rn(x0 - ay0, ay1 - ay0));
        float r1 = rintf(__fdiv_rn(x1 - ax0, ax1 - ax0));
        int i0 = (int)fminf(fmaxf(r0, 0.0f), (float)(GH_-1));
        int i1 = (int)fminf(fmaxf(r1, 0.0f), (float)(GW_-1));
        int flat = (i / U_) * S_ + i0 * GW_ + i1;
        int slot = atomicAdd(&g_counts[flat], 1);
        if (slot < CAP_) g_members[flat*CAP_ + slot] = i;
    } else {
        // ---- fake projection: 8 blocks x 8 warps = 64 warps, 4 outputs each
        const int wid  = tid >> 5;
        const int lane = tid & 31;
        const int fw = (blk - 132) * 8 + wid;      // 0..63
        float f0 = fake[lane];
        float f1 = fake[lane + 32];
        float f2 = fake[lane + 64];
        float f3 = fake[lane + 96];
#pragma unroll
        for (int t = 0; t < 4; t++) {
            int o = fw * 4 + t;                    // 0..255
            int col = o & 127;
            const float* W = (o < 128) ? Wk : Wv;
            float s = f0 * W[lane*128 + col]
                    + f1 * W[(lane+32)*128 + col]
                    + f2 * W[(lane+64)*128 + col]
                    + f3 * W[(lane+96)*128 + col];
#pragma unroll
            for (int d = 16; d > 0; d >>= 1)
                s += __shfl_xor_sync(0xffffffffu, s, d);
            if (lane == 0) {
                if (o < 128) g_Kfake[col] = s;
                else         g_Vfake[col] = s;
            }
        }
    }
}

// ---------------- Stage 2: persistent bf16-split HMMA GEMM ------------------
// Each CTA loads its weight pair into smem ONCE, then loops over NT 64-row
// tiles. D = Ah*Wh + Ah*Wl + Al*Wh (fp32 accum in mma.sync.m16n8k16).
#define WROW 136
#define SM_WORDS (2 * 64 * WROW)          // 17408 u32 = 69632 B
#define DSMEM_BYTES (SM_WORDS * 4)

__global__ void __launch_bounds__(256) gemm_mma(const float* __restrict__ zoff,
                                                const float* __restrict__ zon,
                                                const float* __restrict__ lat,
                                                const float* __restrict__ attnA,
                                                float* __restrict__ outC,
                                                int phase) {
    extern __shared__ uint32_t sw[];       // [0..8703]=hi, [8704..]=lo
    const int tid = threadIdx.x;
    const int blk = blockIdx.x;

    // ---- job decode: weight class + tile range ----
    int wsel, t0, nt;
    if (phase) {              // Wo: 256 tiles over 128 CTAs
        wsel = 3; t0 = blk * 2; nt = 2;
    } else if (blk < 192) {   // Wk class: 768 tiles (512 zoff + 256 zon)
        wsel = 1; t0 = blk * 4; nt = 4;
    } else if (blk < 384) {   // Wv class
        wsel = 2; t0 = (blk - 192) * 4; nt = 4;
    } else {                  // Wq: 64 tiles over 16 CTAs
        wsel = 0; t0 = (blk - 384) * 4; nt = 4;
    }

    // ---- load packed W hi/lo into padded smem (once) ----
    {
        const float4* srcH = (const float4*)g_Wp[wsel][0];
        const float4* srcL = (const float4*)g_Wp[wsel][1];
#pragma unroll
        for (int i = tid; i < 2048; i += 256) {
            int row = i >> 5;
            int c4  = i & 31;
            *(float4*)&sw[row*WROW + c4*4]        = srcH[i];
            *(float4*)&sw[8704 + row*WROW + c4*4] = srcL[i];
        }
    }
    __syncthreads();

    // ---- warp tiling: 8 warps = 4 (M) x 2 (N); warp tile 16x64 ----
    const int wid  = tid >> 5;
    const int lane = tid & 31;
    const int m0 = (wid & 3) * 16;
    const int n0 = (wid >> 2) * 64;
    const int g = lane >> 2;             // 0..7
    const int c = lane & 3;              // 0..3

    for (int ti = 0; ti < nt; ti++) {
        const int t = t0 + ti;
        const float* A;
        float* C;
        if (phase) {
            A = attnA + (size_t)t * 64 * E_;  C = outC + (size_t)t * 64 * E_;
        } else if (wsel == 1) {
            if (t < 512) { A = zoff + (size_t)t * 64 * E_;       C = g_Koff + (size_t)t * 64 * E_; }
            else         { A = zon + (size_t)(t-512) * 64 * E_;  C = g_Kon + (size_t)(t-512) * 64 * E_; }
        } else if (wsel == 2) {
            if (t < 512) { A = zoff + (size_t)t * 64 * E_;       C = g_Voff + (size_t)t * 64 * E_; }
            else         { A = zon + (size_t)(t-512) * 64 * E_;  C = g_Von + (size_t)(t-512) * 64 * E_; }
        } else {
            A = lat + (size_t)t * 64 * E_;  C = g_Q + (size_t)t * 64 * E_;
        }

        float acc[8][4];
#pragma unroll
        for (int i = 0; i < 8; i++)
#pragma unroll
            for (int j = 0; j < 4; j++) acc[i][j] = 0.f;

#pragma unroll
        for (int kc = 0; kc < 8; kc++) {
            const int k0 = kc * 16;
            const float* ar = A + (m0 + g) * E_ + k0 + 2*c;
            float2 x0 = *(const float2*)ar;
            float2 x1 = *(const float2*)(ar + 8*E_);
            float2 x2 = *(const float2*)(ar + 8);
            float2 x3 = *(const float2*)(ar + 8*E_ + 8);
            uint32_t ah[4], al[4];
            ah[0] = pk2(x0.x, x0.y);  al[0] = pk2(resid(x0.x), resid(x0.y));
            ah[1] = pk2(x1.x, x1.y);  al[1] = pk2(resid(x1.x), resid(x1.y));
            ah[2] = pk2(x2.x, x2.y);  al[2] = pk2(resid(x2.x), resid(x2.y));
            ah[3] = pk2(x3.x, x3.y);  al[3] = pk2(resid(x3.x), resid(x3.y));

            const int brow = kc * 8 + c;
#pragma unroll
            for (int ntl = 0; ntl < 8; ntl++) {
                int col = n0 + ntl*8 + g;
                uint32_t bh0 = sw[brow*WROW + col];
                uint32_t bh1 = sw[(brow+4)*WROW + col];
                uint32_t bl0 = sw[8704 + brow*WROW + col];
                uint32_t bl1 = sw[8704 + (brow+4)*WROW + col];
                mma16816(acc[ntl], ah, bh0, bh1);
                mma16816(acc[ntl], ah, bl0, bl1);
                mma16816(acc[ntl], al, bh0, bh1);
            }
        }

        // ---- epilogue ----
#pragma unroll
        for (int ntl = 0; ntl < 8; ntl++) {
            int colb = n0 + ntl*8 + 2*c;
            *(float2*)&C[(m0 + g) * E_ + colb]     = make_float2(acc[ntl][0], acc[ntl][1]);
            *(float2*)&C[(m0 + g + 8) * E_ + colb] = make_float2(acc[ntl][2], acc[ntl][3]);
        }
    }
}

// ---------------- Stage 4: per-bucket attention (1 warp / bucket) -----------
__global__ void __launch_bounds__(128) attn_kernel(const int* __restrict__ ign_p) {
    __shared__ int mem[4][CAP_];
    const int warp = threadIdx.x >> 5;
    const int lane = threadIdx.x & 31;
    const int n = blockIdx.x * 4 + warp;
    const int ign = *ign_p;

    int c = min(g_counts[n], CAP_);
    if (lane < c) mem[warp][lane] = g_members[n*CAP_ + lane];
    __syncwarp();
    if (lane == 0 && c > 1) {           // deterministic order
        int* a = mem[warp];
        for (int i = 1; i < c; i++) {
            int key = a[i]; int j = i - 1;
            while (j >= 0 && a[j] > key) { a[j+1] = a[j]; j--; }
            a[j+1] = key;
        }
    }
    __syncwarp();

    const int s = n & (S_ - 1);
    float4 q = *(const float4*)&g_Q[s*E_ + lane*4];

    const float* klast = ign ? g_Kfake : &g_Kon[n * E_];
    const float* vlast = ign ? g_Vfake : &g_Von[n * E_];

    float m = -INFINITY, lsum = 0.f;
    float4 acc = make_float4(0.f, 0.f, 0.f, 0.f);

    // depth-1 prefetch of K/V rows
    const float* kr = (c > 0) ? &g_Koff[(size_t)mem[warp][0] * E_] : klast;
    const float* vr = (c > 0) ? &g_Voff[(size_t)mem[warp][0] * E_] : vlast;
    float4 kk = *(const float4*)&kr[lane*4];
    float4 vv = *(const float4*)&vr[lane*4];

    for (int p = 0; p <= c; p++) {
        float4 kc = kk, vc = vv;
        if (p < c) {
            const float *kn, *vn;
            if (p + 1 < c) {
                int t = mem[warp][p+1];
                kn = &g_Koff[(size_t)t * E_];
                vn = &g_Voff[(size_t)t * E_];
            } else {
                kn = klast; vn = vlast;
            }
            kk = *(const float4*)&kn[lane*4];
            vv = *(const float4*)&vn[lane*4];
        }
        float d = q.x*kc.x + q.y*kc.y + q.z*kc.z + q.w*kc.w;
        d += __shfl_xor_sync(0xffffffffu, d, 1);
        d += __shfl_xor_sync(0xffffffffu, d, 2);   // head-group (4 lanes) sum
        float sc = d * 0.25f;                      // 1/sqrt(DH=16)
        float mn = fmaxf(m, sc);
        float corr = expf(m - mn);
        float w = expf(sc - mn);
        lsum = lsum * corr + w;
        acc.x = acc.x*corr + w*vc.x;
        acc.y = acc.y*corr + w*vc.y;
        acc.z = acc.z*corr + w*vc.z;
        acc.w = acc.w*corr + w*vc.w;
        m = mn;
    }
    float inv = 1.0f / lsum;
    float4 o = make_float4(acc.x*inv, acc.y*inv, acc.z*inv, acc.w*inv);
    *(float4*)&g_attn[n*E_ + lane*4] = o;
}

// ---------------- launcher ---------------------------------------------------
extern "C" void kernel_launch(void* const* d_in, const int* in_sizes, int n_in,
                              void* d_out, int out_size) {
    const float* xoff = (const float*)d_in[0];
    const float* xon  = (const float*)d_in[1];
    const float* zoff = (const float*)d_in[2];
    const float* zon  = (const float*)d_in[3];
    const float* lat  = (const float*)d_in[4];
    const float* fake = (const float*)d_in[5];
    const float* Wq   = (const float*)d_in[6];
    const float* Wk   = (const float*)d_in[7];
    const float* Wv   = (const float*)d_in[8];
    const float* Wo   = (const float*)d_in[9];
    const int*   ign  = (const int*)d_in[10];
    float* out = (float*)d_out;

    float* pAttn;
    int* pCounts;
    cudaGetSymbolAddress((void**)&pAttn, g_attn);
    cudaGetSymbolAddress((void**)&pCounts, g_counts);

    cudaFuncSetAttribute(gemm_mma,
                         cudaFuncAttributeMaxDynamicSharedMemorySize, DSMEM_BYTES);

    cudaMemsetAsync(pCounts, 0, NB_ * sizeof(int));
    // fused prep: weight split (4) + bucketize (128) + fake proj (8)
    prep_kernel<<<140, 256>>>(Wq, Wk, Wv, Wo, xoff, xon, fake);

    // persistent fused K/V/Q projections: 400 CTAs x 4 tiles
    gemm_mma<<<400, 256, DSMEM_BYTES>>>(zoff, zon, lat, nullptr, nullptr, 0);

    attn_kernel<<<NB_ / 4, 128>>>(ign);

    // output projection: 128 CTAs x 2 tiles
    gemm_mma<<<128, 256, DSMEM_BYTES>>>(nullptr, nullptr, nullptr, pAttn, out, 1);
}